// round 17
// baseline (speedup 1.0000x reference)
#include <cuda_runtime.h>
#include <cuda_fp16.h>
#include <math.h>
#include <stdint.h>

// ---------------- problem constants ----------------
#define SN_     32
#define NROI    512
#define NCH     480
#define TFRM    4
#define FY      45
#define FX      80
#define OSZ     7
#define DIN     23520
#define NDF     1024
#define NCLUS   50
#define KTOT    23520
#define KPAD    23552          // 736 k-tiles of 32 (A padded; B pad tile zero-filled in-kernel)
#define SPLITK  23
#define KT_PER  32             // 736 / 23

// roi split
#define ROIQ    4
#define ROICH   (DIN / ROIQ)   // 5880

// GEMM tiling
#define BM 128
#define BN 128
#define BK 32                  // fp16 elems per k-tile (64B rows)
#define SROW 80                // fp16 tile row: 64B data + 16B pad (conflict-free ldsm)
#define SROWF 144              // f32 B row: 128B data + 16B pad (16B-aligned stride)
#define SUBT_B (BM * SROW)     // 10240
#define OFF_AL 10240
#define OFF_BF 20480
#define STAGE_SZ 38912         // 20480 + 128*144 (=18432)
#define OFF_BH (2 * STAGE_SZ)          // 77824
#define OFF_BL (OFF_BH + SUBT_B)       // 88064
#define SMEM_DYN (OFF_BL + SUBT_B)     // 98304 -> 2 CTAs/SM (196.6 KB of 228 KB)

// ---------------- scratch ----------------
__device__ __align__(128) __half g_pl_hi[(size_t)NROI * KPAD];   // 24 MB
__device__ __align__(128) __half g_pl_lo[(size_t)NROI * KPAD];   // 24 MB
__device__ float g_partial[(size_t)SPLITK * NROI * NDF];         // 48 MB

// ---------------- helpers ----------------
__device__ __forceinline__ uint32_t smem_u32(const void* p) {
    uint32_t a;
    asm("{ .reg .u64 t; cvta.to.shared.u64 t, %1; cvt.u32.u64 %0, t; }" : "=r"(a) : "l"(p));
    return a;
}
__device__ __forceinline__ void cp_async16(uint32_t dst, const void* src) {
    asm volatile("cp.async.cg.shared.global [%0], [%1], 16;" :: "r"(dst), "l"(src) : "memory");
}
__device__ __forceinline__ void cp_commit() {
    asm volatile("cp.async.commit_group;" ::: "memory");
}
template <int N>
__device__ __forceinline__ void cp_wait() {
    asm volatile("cp.async.wait_group %0;" :: "n"(N) : "memory");
}
__device__ __forceinline__ void ldsm_x4(uint32_t* r, uint32_t addr) {
    asm volatile("ldmatrix.sync.aligned.m8n8.x4.shared.b16 {%0,%1,%2,%3}, [%4];"
                 : "=r"(r[0]), "=r"(r[1]), "=r"(r[2]), "=r"(r[3]) : "r"(addr));
}
__device__ __forceinline__ void mma_f16(float* c, const uint32_t* a, uint32_t b0, uint32_t b1) {
    asm volatile(
        "mma.sync.aligned.m16n8k16.row.col.f32.f16.f16.f32 "
        "{%0,%1,%2,%3}, {%4,%5,%6,%7}, {%8,%9}, {%0,%1,%2,%3};"
        : "+f"(c[0]), "+f"(c[1]), "+f"(c[2]), "+f"(c[3])
        : "r"(a[0]), "r"(a[1]), "r"(a[2]), "r"(a[3]), "r"(b0), "r"(b1));
}
__device__ __forceinline__ float nan_to_num(float v) {
    if (isnan(v)) return 0.0f;
    if (isinf(v)) return v > 0.0f ? 3.4028234663852886e38f : -3.4028234663852886e38f;
    return v;
}
// split two floats -> packed fp16 hi pair + lo pair
__device__ __forceinline__ void split2(float x, float y, uint32_t& hi, uint32_t& lo) {
    __half2 h = __floats2half2_rn(x, y);
    float2 hf = __half22float2(h);
    __half2 l = __floats2half2_rn(x - hf.x, y - hf.y);
    hi = *(uint32_t*)&h;
    lo = *(uint32_t*)&l;
}

// ---------------- kernel 1: quarter-RoI-align -> pooled hi/lo fp16 ----------------
__global__ void roi_pool_kernel(const float* __restrict__ zvis,
                                const float* __restrict__ bboxs) {
    __shared__ int   s_off[49][4];
    __shared__ float s_w[49][4];

    const int bid = blockIdx.x;
    const int tid = threadIdx.x;
    const int r = bid >> 2;           // roi index
    const int q = bid & 3;            // quarter index
    const int b = r / SN_;

    if (tid < 49) {
        const float* bb = bboxs + (size_t)r * 4;
        const float sc = 0.0625f;
        float x1 = nan_to_num(bb[0] * sc) - 0.5f;
        float y1 = nan_to_num(bb[1] * sc) - 0.5f;
        float x2 = nan_to_num(bb[2] * sc) - 0.5f;
        float y2 = nan_to_num(bb[3] * sc) - 0.5f;
        float bw = (x2 - x1) * (1.0f / OSZ);
        float bh = (y2 - y1) * (1.0f / OSZ);

        int py = tid / OSZ, px = tid - py * OSZ;
        float y = y1 + ((float)py + 0.5f) * bh;
        float x = x1 + ((float)px + 0.5f) * bw;
        bool valid = (y > -1.0f) && (y < (float)FY) && (x > -1.0f) && (x < (float)FX);
        float yc = fminf(fmaxf(y, 0.0f), (float)(FY - 1));
        float xc = fminf(fmaxf(x, 0.0f), (float)(FX - 1));
        int yl = (int)floorf(yc);
        int xl = (int)floorf(xc);
        int yh = min(yl + 1, FY - 1);
        int xh = min(xl + 1, FX - 1);
        float ly = yc - (float)yl, lx = xc - (float)xl;
        float hy = 1.0f - ly, hx = 1.0f - lx;
        float vm = valid ? 1.0f : 0.0f;

        s_off[tid][0] = yl * FX + xl;
        s_off[tid][1] = yl * FX + xh;
        s_off[tid][2] = yh * FX + xl;
        s_off[tid][3] = yh * FX + xh;
        s_w[tid][0] = hy * hx * vm;
        s_w[tid][1] = hy * lx * vm;
        s_w[tid][2] = ly * hx * vm;
        s_w[tid][3] = ly * lx * vm;
    }
    __syncthreads();

    const float* fbase = zvis + (size_t)b * NCH * TFRM * FY * FX + (size_t)3 * FY * FX;
    __half* ohi = g_pl_hi + (size_t)r * KPAD;
    __half* olo = g_pl_lo + (size_t)r * KPAD;

    const int kend = (q + 1) * ROICH;
    for (int k = q * ROICH + tid; k < kend; k += 256) {
        int c = k / 49;
        int p = k - c * 49;
        const float* f = fbase + (size_t)c * (TFRM * FY * FX);
        float v = s_w[p][0] * f[s_off[p][0]]
                + s_w[p][1] * f[s_off[p][1]]
                + s_w[p][2] * f[s_off[p][2]]
                + s_w[p][3] * f[s_off[p][3]];
        __half h = __float2half_rn(v);
        ohi[k] = h;
        olo[k] = __float2half_rn(v - __half2float(h));
    }
    if (q == 3 && tid < (KPAD - DIN)) {
        ohi[DIN + tid] = __float2half_rn(0.0f);
        olo[DIN + tid] = __float2half_rn(0.0f);
    }
}

// ---------------- kernel 2: fp16 three-term HMMA GEMM, B from f32 w_vis ----------------
// acc = Ah*Bh + Al*Bh + Ah*Bl.  A: cp.async fp16 hi/lo.  B: cp.async f32 +
// in-smem split to Bh/Bl each k-tile (single-buffered conversion area).
__global__ void __launch_bounds__(256, 2) gemm_hmma(const float* __restrict__ Wv) {
    extern __shared__ __align__(16) char smem[];

    const int tid   = threadIdx.x;
    const int warp  = tid >> 5;
    const int lane  = tid & 31;
    const int nBase = blockIdx.x * BN;
    const int mBase = blockIdx.y * BM;
    const int z     = blockIdx.z;

    const uint32_t sbase = smem_u32(smem);

    // A loader mapping
    const int lrow = tid >> 2;        // 0..63
    const int lseg = tid & 3;         // 16B segment
    // B loader / converter mapping: 2 threads per B row
    const int brw = tid >> 1;         // 0..127
    const int bhf = tid & 1;          // k-half (16 floats = 64B)

    // compute mapping
    const int warpM = warp >> 2;      // 0..1 -> *64
    const int warpN = warp & 3;       // 0..3 -> *32
    const uint32_t a_row = (uint32_t)(warpM * 64 + (lane & 15));
    const uint32_t a_seg = (uint32_t)(lane >> 4);
    const uint32_t b_row = (uint32_t)(warpN * 32 + ((lane >> 4) << 3) + (lane & 7));
    const uint32_t b_seg = (uint32_t)((lane >> 3) & 1);

    float acc[4][4][4];
    #pragma unroll
    for (int i = 0; i < 4; ++i)
        #pragma unroll
        for (int j = 0; j < 4; ++j)
            #pragma unroll
            for (int q = 0; q < 4; ++q) acc[i][j][q] = 0.0f;

    auto load_stage = [&](int s, int kt) {
        const int koff = (z * KT_PER + kt) * BK;     // in elements
        const uint32_t st = sbase + s * STAGE_SZ;
        // A (always valid: padded arrays)
        const __half* ah0 = g_pl_hi + (size_t)(mBase + lrow)      * KPAD + koff + lseg * 8;
        const __half* ah1 = g_pl_hi + (size_t)(mBase + lrow + 64) * KPAD + koff + lseg * 8;
        const __half* al0 = g_pl_lo + (size_t)(mBase + lrow)      * KPAD + koff + lseg * 8;
        const __half* al1 = g_pl_lo + (size_t)(mBase + lrow + 64) * KPAD + koff + lseg * 8;
        cp_async16(st +          lrow * SROW        + lseg * 16, ah0);
        cp_async16(st +         (lrow + 64) * SROW  + lseg * 16, ah1);
        cp_async16(st + OFF_AL + lrow * SROW        + lseg * 16, al0);
        cp_async16(st + OFF_AL + (lrow + 64) * SROW + lseg * 16, al1);
        // B f32: row brw, half bhf -> 4 chunks of 16B
        if (koff < KTOT) {
            const float* bp = Wv + (size_t)(nBase + brw) * KTOT + koff + bhf * 16;
            #pragma unroll
            for (int j = 0; j < 4; ++j)
                cp_async16(st + OFF_BF + brw * SROWF + bhf * 64 + j * 16, bp + j * 4);
        } else {
            // pad tile: zero-fill via STS (visible after the next barrier)
            #pragma unroll
            for (int j = 0; j < 4; ++j)
                *(uint4*)(smem + s * STAGE_SZ + OFF_BF + brw * SROWF + bhf * 64 + j * 16)
                    = make_uint4(0, 0, 0, 0);
        }
        cp_commit();
    };

    // prologue
    load_stage(0, 0);

    for (int kt = 0; kt < KT_PER; ++kt) {
        cp_wait<0>();
        __syncthreads();       // stage kt resident; all reads of other buffer + BhBl done
        if (kt + 1 < KT_PER) load_stage((kt + 1) & 1, kt + 1);

        // convert B f32 (stage kt) -> Bh/Bl fp16 (single-buffered)
        {
            const char* sf = smem + (kt & 1) * STAGE_SZ + OFF_BF + brw * SROWF + bhf * 64;
            float4 f0 = *(const float4*)(sf);
            float4 f1 = *(const float4*)(sf + 16);
            float4 f2 = *(const float4*)(sf + 32);
            float4 f3 = *(const float4*)(sf + 48);
            uint4 hA, lA, hB, lB;
            split2(f0.x, f0.y, hA.x, lA.x);  split2(f0.z, f0.w, hA.y, lA.y);
            split2(f1.x, f1.y, hA.z, lA.z);  split2(f1.z, f1.w, hA.w, lA.w);
            split2(f2.x, f2.y, hB.x, lB.x);  split2(f2.z, f2.w, hB.y, lB.y);
            split2(f3.x, f3.y, hB.z, lB.z);  split2(f3.z, f3.w, hB.w, lB.w);
            char* dh = smem + OFF_BH + brw * SROW + bhf * 32;
            char* dl = smem + OFF_BL + brw * SROW + bhf * 32;
            *(uint4*)(dh)      = hA;  *(uint4*)(dh + 16) = hB;
            *(uint4*)(dl)      = lA;  *(uint4*)(dl + 16) = lB;
        }
        __syncthreads();       // conversions visible

        const uint32_t st  = sbase + (kt & 1) * STAGE_SZ;
        const uint32_t sah = st;
        const uint32_t sal = st + OFF_AL;
        const uint32_t sbh = sbase + OFF_BH;
        const uint32_t sbl = sbase + OFF_BL;

        #pragma unroll
        for (int ks = 0; ks < 2; ++ks) {
            uint32_t bh[2][4], bl[2][4];
            #pragma unroll
            for (int pr = 0; pr < 2; ++pr) {
                ldsm_x4(bh[pr], sbh + (b_row + pr * 16) * SROW + (ks * 2 + b_seg) * 16);
                ldsm_x4(bl[pr], sbl + (b_row + pr * 16) * SROW + (ks * 2 + b_seg) * 16);
            }

            uint32_t ah[4][4], al[4][4];
            #pragma unroll
            for (int mf = 0; mf < 4; ++mf) {
                ldsm_x4(ah[mf], sah + (a_row + mf * 16) * SROW + (ks * 2 + a_seg) * 16);
                ldsm_x4(al[mf], sal + (a_row + mf * 16) * SROW + (ks * 2 + a_seg) * 16);
            }

            #pragma unroll
            for (int mf = 0; mf < 4; ++mf)
                #pragma unroll
                for (int nf = 0; nf < 4; ++nf)
                    mma_f16(acc[mf][nf], ah[mf], bh[nf >> 1][(nf & 1) * 2], bh[nf >> 1][(nf & 1) * 2 + 1]);
            #pragma unroll
            for (int mf = 0; mf < 4; ++mf)
                #pragma unroll
                for (int nf = 0; nf < 4; ++nf)
                    mma_f16(acc[mf][nf], al[mf], bh[nf >> 1][(nf & 1) * 2], bh[nf >> 1][(nf & 1) * 2 + 1]);
            #pragma unroll
            for (int mf = 0; mf < 4; ++mf)
                #pragma unroll
                for (int nf = 0; nf < 4; ++nf)
                    mma_f16(acc[mf][nf], ah[mf], bl[nf >> 1][(nf & 1) * 2], bl[nf >> 1][(nf & 1) * 2 + 1]);
        }
    }

    // epilogue -> g_partial[z][m][n]
    const int group = lane >> 2;
    const int quad  = lane & 3;
    #pragma unroll
    for (int mf = 0; mf < 4; ++mf) {
        int row0 = mBase + warpM * 64 + mf * 16 + group;
        #pragma unroll
        for (int nf = 0; nf < 4; ++nf) {
            int col = nBase + warpN * 32 + nf * 8 + quad * 2;
            float* p0 = g_partial + ((size_t)z * NROI + row0) * NDF + col;
            float* p1 = p0 + (size_t)8 * NDF;
            *(float2*)p0 = make_float2(acc[mf][nf][0], acc[mf][nf][1]);
            *(float2*)p1 = make_float2(acc[mf][nf][2], acc[mf][nf][3]);
        }
    }
}

// ---------------- kernel 3: fused reduce + bias + cluster (4 rois/block) ----------------
__global__ void cluster_fused_kernel(const float* __restrict__ norms,
                                     const float* __restrict__ b_vis,
                                     const float* __restrict__ w_spc,
                                     const float* __restrict__ b_spc,
                                     const float* __restrict__ cent,
                                     float* __restrict__ Z,
                                     float* __restrict__ out_s,
                                     float* __restrict__ out_c) {
    __shared__ __align__(16) float zrow[4][NDF];
    __shared__ float sdist[4][NCLUS];
    __shared__ float ssum[4];
    __shared__ int   sarg[4];

    const int m0  = blockIdx.x * 4;
    const int tid = threadIdx.x;
    float nm[4];
    #pragma unroll
    for (int j = 0; j < 4; ++j) nm[j] = norms[m0 + j];

    for (int d = tid; d < NDF; d += 256) {
        float base = b_vis[d] + b_spc[d];
        float w = w_spc[d];
        float a[4];
        #pragma unroll
        for (int j = 0; j < 4; ++j) a[j] = base + nm[j] * w;
        for (int zz = 0; zz < SPLITK; ++zz) {
            const float* pp = g_partial + ((size_t)zz * NROI + m0) * NDF + d;
            #pragma unroll
            for (int j = 0; j < 4; ++j) a[j] += pp[(size_t)j * NDF];
        }
        #pragma unroll
        for (int j = 0; j < 4; ++j) {
            zrow[j][d] = a[j];
            Z[(size_t)(m0 + j) * NDF + d] = a[j];
        }
    }
    __syncthreads();

    const int warp = tid >> 5;
    const int lane = tid & 31;
    for (int k = warp; k < NCLUS; k += 8) {
        const float4* ck = (const float4*)(cent + (size_t)k * NDF);
        float s[4] = {0.f, 0.f, 0.f, 0.f};
        #pragma unroll
        for (int i = 0; i < 8; ++i) {
            int d4 = i * 32 + lane;
            float4 c = ck[d4];
            #pragma unroll
            for (int j = 0; j < 4; ++j) {
                float4 zv = *(const float4*)&zrow[j][d4 * 4];
                float t;
                t = zv.x - c.x; s[j] += t * t;
                t = zv.y - c.y; s[j] += t * t;
                t = zv.z - c.z; s[j] += t * t;
                t = zv.w - c.w; s[j] += t * t;
            }
        }
        #pragma unroll
        for (int o = 16; o; o >>= 1)
            #pragma unroll
            for (int j = 0; j < 4; ++j)
                s[j] += __shfl_xor_sync(0xffffffffu, s[j], o);
        if (lane == 0)
            #pragma unroll
            for (int j = 0; j < 4; ++j) sdist[j][k] = sqrtf(s[j]);
    }
    __syncthreads();

    if (tid < 4) {
        float sum = 0.0f, best = -1.0f;
        int bi = 0;
        for (int k = 0; k < NCLUS; ++k) {
            float st = 1.0f / (1.0f + sdist[tid][k]);
            sum += st;
            if (st > best) { best = st; bi = k; }
        }
        ssum[tid] = sum;
        sarg[tid] = bi;
    }
    __syncthreads();

    {
        const int j = tid >> 6;          // 0..3
        const int kk = tid & 63;         // 0..63
        if (kk < NCLUS)
            out_s[(size_t)(m0 + j) * NCLUS + kk] = (1.0f / (1.0f + sdist[j][kk])) / ssum[j];
    }
    if (tid < 4) out_c[m0 + tid] = (float)sarg[tid];
}

// ---------------- launch ----------------
extern "C" void kernel_launch(void* const* d_in, const int* in_sizes, int n_in,
                              void* d_out, int out_size) {
    const float* z_vis     = (const float*)d_in[0];
    const float* bboxs     = (const float*)d_in[1];
    const float* norms     = (const float*)d_in[2];
    const float* w_vis     = (const float*)d_in[3];
    const float* b_vis     = (const float*)d_in[4];
    const float* w_spc     = (const float*)d_in[5];
    const float* b_spc     = (const float*)d_in[6];
    const float* centroids = (const float*)d_in[7];

    float* out = (float*)d_out;
    float* Z = out;
    float* S = out + (size_t)NROI * NDF;
    float* C = S + (size_t)NROI * NCLUS;

    cudaFuncSetAttribute(gemm_hmma, cudaFuncAttributeMaxDynamicSharedMemorySize, SMEM_DYN);

    roi_pool_kernel<<<NROI * ROIQ, 256>>>(z_vis, bboxs);

    dim3 gg(NDF / BN, NROI / BM, SPLITK);        // (8, 4, 23) = 736 CTAs, 2/SM
    gemm_hmma<<<gg, 256, SMEM_DYN>>>(w_vis);

    cluster_fused_kernel<<<NROI / 4, 256>>>(norms, b_vis, w_spc, b_spc, centroids, Z, S, C);
}